// round 10
// baseline (speedup 1.0000x reference)
#include <cuda_runtime.h>
#include <cuda_bf16.h>
#include <cuda_fp16.h>
#include <cstdint>

typedef unsigned long long ull;

// Problem constants (fixed shapes)
#define BB   64
#define TT   256
#define VV   10000
#define VPAD 10240
#define EE   100
#define HH   128
#define GG   512          // 4H
#define BT   (BB*TT)      // 16384
#define KSPLIT 256        // fp16 2-term: A=[h_hi|h_lo], B=[w_hi|w_hi]

#define LOGITS_ELEMS ((size_t)BT * VV)          // 163,840,000
#define HF_OFF  LOGITS_ELEMS
#define CF_OFF  (LOGITS_ELEMS + (size_t)BB*HH)
#define FULL_OUT (LOGITS_ELEMS + 2ull*BB*HH)

// Scratch (device globals; allocation-free per harness rules)
__device__ float  g_xproj[(size_t)BT * GG];          // 33.5 MB
__device__ __half g_hs_split[(size_t)BT * KSPLIT];   // 8.4 MB  [bt][hi|lo]
__device__ __half g_wfc_split[(size_t)VPAD * KSPLIT];// 5.2 MB  [v][hi|hi]

// ---------------------------------------------------------------------------
// Helpers
// ---------------------------------------------------------------------------
__device__ __forceinline__ uint32_t smem_u32(const void* p) {
    uint32_t a;
    asm("{ .reg .u64 t; cvta.to.shared.u64 t, %1; cvt.u32.u64 %0, t; }" : "=r"(a) : "l"(p));
    return a;
}
__device__ __forceinline__ void cp16(uint32_t dst, const void* src) {
    asm volatile("cp.async.cg.shared.global [%0], [%1], 16;" :: "r"(dst), "l"(src));
}
#define CP_COMMIT() asm volatile("cp.async.commit_group;" ::: "memory")
#define CP_WAIT(n)  asm volatile("cp.async.wait_group %0;" :: "n"(n) : "memory")

__device__ __forceinline__ void ldm4(uint32_t* r, uint32_t addr) {
    asm volatile("ldmatrix.sync.aligned.m8n8.x4.shared.b16 {%0,%1,%2,%3}, [%4];"
                 : "=r"(r[0]), "=r"(r[1]), "=r"(r[2]), "=r"(r[3]) : "r"(addr));
}
__device__ __forceinline__ void mma16816(float* c, const uint32_t* a,
                                         uint32_t b0, uint32_t b1) {
    asm volatile(
        "mma.sync.aligned.m16n8k16.row.col.f32.f16.f16.f32 "
        "{%0,%1,%2,%3}, {%4,%5,%6,%7}, {%8,%9}, {%0,%1,%2,%3};"
        : "+f"(c[0]), "+f"(c[1]), "+f"(c[2]), "+f"(c[3])
        : "r"(a[0]), "r"(a[1]), "r"(a[2]), "r"(a[3]), "r"(b0), "r"(b1));
}
__device__ __forceinline__ ull fma2_(ull a, ull b, ull c) {
    ull d;
    asm("fma.rn.f32x2 %0, %1, %2, %3;" : "=l"(d) : "l"(a), "l"(b), "l"(c));
    return d;
}
__device__ __forceinline__ void unpack2_(ull v, float& x, float& y) {
    asm("mov.b64 {%0, %1}, %2;" : "=f"(x), "=f"(y) : "l"(v));
}

// Fast, saturation-safe activations (MUFU EX2 based)
__device__ __forceinline__ float sigm_fast(float x) {
    return 1.f / (1.f + __expf(-x));
}
__device__ __forceinline__ float tanh_fast(float x) {
    return 2.f / (1.f + __expf(-2.f * x)) - 1.f;
}

// Cluster / DSMEM / mbarrier primitives (base PTX, sm_90+; no 'a'-suffix needed)
__device__ __forceinline__ uint32_t mapa_peer(uint32_t laddr, uint32_t peer) {
    uint32_t r;
    asm("mapa.shared::cluster.u32 %0, %1, %2;" : "=r"(r) : "r"(laddr), "r"(peer));
    return r;
}
__device__ __forceinline__ void st_cluster_f32(uint32_t raddr, float v) {
    asm volatile("st.shared::cluster.f32 [%0], %1;" :: "r"(raddr), "f"(v) : "memory");
}
__device__ __forceinline__ void mbar_arrive_cluster(uint32_t raddr) {
    asm volatile("mbarrier.arrive.release.cluster.shared::cluster.b64 _, [%0];"
                 :: "r"(raddr) : "memory");
}
#define MBARRIER_INIT(mbar, count) \
    asm volatile("mbarrier.init.shared.b64 [%0], %1;" \
                 :: "r"((uint32_t)(mbar)), "r"((uint32_t)(count)) : "memory")
#define MBAR_WAIT_CLUSTER(mbar, parity) do {                                      \
    uint32_t _m = (uint32_t)(mbar); uint32_t _p = (uint32_t)(parity);             \
    asm volatile("{\n\t.reg .pred P1;\n\t"                                        \
        "WAIT_LOOP_%=:\n\t"                                                       \
        "mbarrier.try_wait.parity.acquire.cluster.shared::cta.b64 P1, [%0], %1, 0x989680;\n\t" \
        "@P1 bra.uni WAIT_DONE_%=;\n\t"                                           \
        "bra.uni WAIT_LOOP_%=;\n\t"                                               \
        "WAIT_DONE_%=:\n\t}"                                                      \
        :: "r"(_m), "r"(_p) : "memory");                                          \
} while (0)
#define CLUSTER_SYNC() do { \
    asm volatile("barrier.cluster.arrive.aligned;" ::: "memory"); \
    asm volatile("barrier.cluster.wait.aligned;" ::: "memory"); \
} while (0)

// ---------------------------------------------------------------------------
// Kernel 1: embedding gather + input projection
// ---------------------------------------------------------------------------
__global__ __launch_bounds__(512) void k_embed_proj(
    const int* __restrict__ x, const float* __restrict__ emb,
    const float* __restrict__ W_ih, const float* __restrict__ b_ih,
    const float* __restrict__ b_hh)
{
    __shared__ float xe_s[16 * EE];
    __shared__ int   toks[16];
    const int bt0 = blockIdx.x * 16;
    const int tid = threadIdx.x;

    if (tid < 16) toks[tid] = x[bt0 + tid];
    __syncthreads();
    for (int i = tid; i < 16 * EE; i += 512) {
        int r = i / EE, e = i - r * EE;
        xe_s[i] = emb[(size_t)toks[r] * EE + e];
    }
    __syncthreads();

    const int g = tid;
    float acc[16];
#pragma unroll
    for (int r = 0; r < 16; r++) acc[r] = 0.f;

    const float4* W4 = reinterpret_cast<const float4*>(W_ih + (size_t)g * EE);
#pragma unroll 5
    for (int e4 = 0; e4 < EE / 4; e4++) {
        float4 w = W4[e4];
#pragma unroll
        for (int r = 0; r < 16; r++) {
            float4 v = reinterpret_cast<const float4*>(xe_s + r * EE)[e4];
            acc[r] += w.x * v.x;
            acc[r] += w.y * v.y;
            acc[r] += w.z * v.z;
            acc[r] += w.w * v.w;
        }
    }
    const float bias = b_ih[g] + b_hh[g];
#pragma unroll
    for (int r = 0; r < 16; r++)
        g_xproj[(size_t)(bt0 + r) * GG + g] = acc[r] + bias;
}

// ---------------------------------------------------------------------------
// Kernel 2: LSTM recurrence, 2-CTA cluster per batch, DSMEM h exchange.
// CTA rank r owns hidden units [r*64, r*64+64): all 4 gates, W fully in regs.
// Thread layout: tid = j*4 + q (j local unit 0..63, q gate i/f/g/o).
// Gate exchange via 3x shfl_xor within 4-lane groups; c replicated per lane.
// h double-buffered (hbuf[2]); publish via st.shared::cluster +
// mbarrier.arrive.release.cluster (count=64); wait parity (t>>1)&1.
// ---------------------------------------------------------------------------
__global__ __launch_bounds__(256, 1) __cluster_dims__(2, 1, 1)
void k_lstm(const float* __restrict__ W_hh, float* __restrict__ out,
            long long out_size)
{
    __shared__ __align__(16) float hbuf[2][HH];
    __shared__ __align__(8)  ull   mbar[2];

    const int tid  = threadIdx.x;
    const int q    = tid & 3;               // gate: 0=i 1=f 2=g 3=o
    const int j    = tid >> 2;              // local unit 0..63
    uint32_t rank;
    asm("mov.u32 %0, %%cluster_ctarank;" : "=r"(rank));
    const int b    = blockIdx.x >> 1;       // cluster id = batch
    const int unit = (int)rank * 64 + j;    // global hidden unit 0..127
    const int row  = q * HH + unit;         // W_hh / gate row 0..511

    // W_hh[row][0..127] fully register-resident as 64 packed f32x2
    ull w[64];
    {
        const ulonglong2* Wg = reinterpret_cast<const ulonglong2*>(W_hh + (size_t)row * HH);
#pragma unroll
        for (int i = 0; i < 32; i++) {
            ulonglong2 u = Wg[i];
            w[2 * i]     = u.x;
            w[2 * i + 1] = u.y;
        }
    }

    if (tid < HH) { hbuf[0][tid] = 0.f; hbuf[1][tid] = 0.f; }
    if (tid == 0) {
        MBARRIER_INIT(smem_u32(&mbar[0]), 64);
        MBARRIER_INIT(smem_u32(&mbar[1]), 64);
    }
    __syncthreads();
    CLUSTER_SYNC();   // peer mbar init visible before any remote arrive

    // Precomputed addresses
    const uint32_t l_h0 = smem_u32(&hbuf[0][unit]);
    const uint32_t l_h1 = smem_u32(&hbuf[1][unit]);
    const uint32_t r_h0 = mapa_peer(l_h0, rank ^ 1);
    const uint32_t r_h1 = mapa_peer(l_h1, rank ^ 1);
    const uint32_t l_m0 = smem_u32(&mbar[0]);
    const uint32_t l_m1 = smem_u32(&mbar[1]);
    const uint32_t r_m0 = mapa_peer(l_m0, rank ^ 1);
    const uint32_t r_m1 = mapa_peer(l_m1, rank ^ 1);

    const float* xp = g_xproj + (size_t)b * TT * GG;
    float xnext = xp[row];                   // prefetch t=0
    float c = 0.f;                           // replicated across the 4 gate lanes
    float hlast = 0.f;

    for (int t = 0; t < TT; t++) {
        const ulonglong2* h2 = reinterpret_cast<const ulonglong2*>(hbuf[t & 1]);

        ull acc2a = 0ull, acc2b = 0ull;
#pragma unroll
        for (int i = 0; i < 32; i++) {
            ulonglong2 hp = h2[i];           // LDS.128 broadcast
            acc2a = fma2_(w[2 * i],     hp.x, acc2a);
            acc2b = fma2_(w[2 * i + 1], hp.y, acc2b);
        }
        float l0, h0, l1, h1;
        unpack2_(acc2a, l0, h0);
        unpack2_(acc2b, l1, h1);
        const float gv = xnext + ((l0 + l1) + (h0 + h1));
        if (t + 1 < TT) xnext = __ldg(xp + (t + 1) * GG + row);

        const float v = (q == 2) ? tanh_fast(gv) : sigm_fast(gv);
        const float a1 = __shfl_xor_sync(0xFFFFFFFFu, v, 1);
        const float a2 = __shfl_xor_sync(0xFFFFFFFFu, v, 2);
        const float a3 = __shfl_xor_sync(0xFFFFFFFFu, v, 3);
        const float ig = (q == 0) ? v  : (q == 1) ? a1 : (q == 2) ? a2 : a3;
        const float fg = (q == 0) ? a1 : (q == 1) ? v  : (q == 2) ? a3 : a2;
        const float gg = (q == 0) ? a2 : (q == 1) ? a3 : (q == 2) ? v  : a1;
        const float og = (q == 0) ? a3 : (q == 1) ? a2 : (q == 2) ? a1 : v;

        c = fg * c + ig * gg;
        const float h = og * tanh_fast(c);
        hlast = h;

        __syncthreads();                     // all reads of hbuf[t&1] complete
        const int nb = (t + 1) & 1;
        if (q == 0) {
            hbuf[nb][unit] = h;                          // local
            st_cluster_f32(nb ? r_h1 : r_h0, h);         // peer
            // fp16 split for logits GEMM
            __half hh = __float2half_rn(h);
            float  hl = h - __half2float(hh);
            size_t base = ((size_t)b * TT + t) * KSPLIT;
            g_hs_split[base + unit]       = hh;
            g_hs_split[base + 128 + unit] = __float2half_rn(hl);
            mbar_arrive_cluster(nb ? r_m1 : r_m0);       // publish to peer
        }
        __syncthreads();                     // local hbuf[nb] stores visible
        MBAR_WAIT_CLUSTER(nb ? l_m1 : l_m0, (t >> 1) & 1);  // peer's 64 h arrived
    }

    if (q == 0 && out_size >= (long long)FULL_OUT) {
        out[HF_OFF + (size_t)b * HH + unit] = hlast;
        out[CF_OFF + (size_t)b * HH + unit] = c;
    }
    CLUSTER_SYNC();   // no CTA exits while peer stores may target its smem
}

// ---------------------------------------------------------------------------
// Kernel 2b: W_fc -> fp16 hi duplicated [hi|hi], zero-padded to VPAD rows
// ---------------------------------------------------------------------------
__global__ __launch_bounds__(256) void k_split_wfc(const float* __restrict__ W_fc)
{
    size_t i = (size_t)blockIdx.x * 256 + threadIdx.x;   // over VPAD*HH
    int v = (int)(i >> 7);
    int k = (int)(i & 127);
    float w = (v < VV) ? W_fc[i] : 0.f;
    __half hi = __float2half_rn(w);
    size_t base = (size_t)v * KSPLIT;
    g_wfc_split[base + k]       = hi;
    g_wfc_split[base + 128 + k] = hi;
}

// ---------------------------------------------------------------------------
// Kernel 3: logits GEMM via mma.sync (fp16 2-term K=256, fp32 accum)
// 128x128 block tile, BK=64 chunks (4), 3-stage cp.async ring, 2 CTA/SM.
// 8 warps as 2(m) x 4(n); warp tile 64x32.
// ---------------------------------------------------------------------------
#define NK 4
#define STAGE_BYTES 32768          // A 16KB + B 16KB
#define SMEM3_BYTES (3 * STAGE_BYTES)

__device__ __forceinline__ void load_chunk(
    uint32_t smem_base, int stage,
    const __half* __restrict__ asrc,   // + bt0*KSPLIT
    const __half* __restrict__ bsrc,   // + v0*KSPLIT
    int kc, int tid)
{
    const int abuf = stage * STAGE_BYTES;
    const int bbuf = abuf + 16384;
    const int k0 = kc * 64;
#pragma unroll
    for (int it = 0; it < 4; it++) {
        int i = tid + it * 256;          // 0..1023
        int row = i >> 3;
        int jj  = i & 7;
        uint32_t dst = smem_base + abuf + row * 128 + ((jj ^ (row & 7)) << 4);
        cp16(dst, asrc + (size_t)row * KSPLIT + k0 + jj * 8);
    }
#pragma unroll
    for (int it = 0; it < 4; it++) {
        int i = tid + it * 256;
        int row = i >> 3;
        int jj  = i & 7;
        uint32_t dst = smem_base + bbuf + row * 128 + ((jj ^ (row & 7)) << 4);
        cp16(dst, bsrc + (size_t)row * KSPLIT + k0 + jj * 8);
    }
}

__global__ __launch_bounds__(256, 2) void k_logits_mma(
    const float* __restrict__ b_fc, float* __restrict__ out)
{
    extern __shared__ char smem3[];
    const uint32_t smem_base = smem_u32(smem3);
    const int tid = threadIdx.x;
    const int wid = tid >> 5;
    const int l   = tid & 31;
    const int v0  = blockIdx.x * 128;
    const int bt0 = blockIdx.y * 128;

    const __half* asrc = g_hs_split + (size_t)bt0 * KSPLIT;
    const __half* bsrc = g_wfc_split + (size_t)v0 * KSPLIT;

    const int wm = (wid >> 2) * 64;   // warp m offset (0/64)
    const int wn = (wid & 3) * 32;    // warp n offset (0..96)

    float c[4][4][4];
#pragma unroll
    for (int mi = 0; mi < 4; mi++)
#pragma unroll
        for (int nj = 0; nj < 4; nj++)
#pragma unroll
            for (int qq = 0; qq < 4; qq++) c[mi][nj][qq] = 0.f;

    const int lrow = l & 15;
    const int lsel = l >> 4;

    // prologue: 2 stages in flight
    load_chunk(smem_base, 0, asrc, bsrc, 0, tid);
    CP_COMMIT();
    load_chunk(smem_base, 1, asrc, bsrc, 1, tid);
    CP_COMMIT();

#pragma unroll
    for (int kc = 0; kc < NK; kc++) {
        if (kc < NK - 1) { CP_WAIT(1); } else { CP_WAIT(0); }
        __syncthreads();                       // chunk kc visible; kc-1 compute done
        if (kc + 2 < NK) {
            load_chunk(smem_base, (kc + 2) % 3, asrc, bsrc, kc + 2, tid);
            CP_COMMIT();
        }

        const int abuf = (kc % 3) * STAGE_BYTES;
        const int bbuf = abuf + 16384;
#pragma unroll
        for (int k16 = 0; k16 < 4; k16++) {
            const int jj = 2 * k16 + lsel;
            uint32_t a[4][4];
#pragma unroll
            for (int mi = 0; mi < 4; mi++) {
                int r = wm + mi * 16 + lrow;
                ldm4(a[mi], smem_base + abuf + r * 128 + ((jj ^ (r & 7)) << 4));
            }
            uint32_t bfr[2][4];
#pragma unroll
            for (int njp = 0; njp < 2; njp++) {
                int r = wn + njp * 16 + lrow;
                ldm4(bfr[njp], smem_base + bbuf + r * 128 + ((jj ^ (r & 7)) << 4));
            }
#pragma unroll
            for (int mi = 0; mi < 4; mi++) {
#pragma unroll
                for (int njp = 0; njp < 2; njp++) {
                    mma16816(c[mi][njp * 2 + 0], a[mi], bfr[njp][0], bfr[njp][2]);
                    mma16816(c[mi][njp * 2 + 1], a[mi], bfr[njp][1], bfr[njp][3]);
                }
            }
        }
    }

    // Epilogue: bias + guarded float2 stores
    const int g  = l >> 2;
    const int qq = l & 3;
    const int mB = bt0 + wm;
    const int nB = v0 + wn;

#pragma unroll
    for (int nj = 0; nj < 4; nj++) {
        const int v = nB + nj * 8 + 2 * qq;
        if (v >= VV) continue;
        const float2 bias = *reinterpret_cast<const float2*>(b_fc + v);
#pragma unroll
        for (int mi = 0; mi < 4; mi++) {
            const float* cc = c[mi][nj];
            const int r0 = mB + mi * 16 + g;
            float2 o0 = make_float2(cc[0] + bias.x, cc[1] + bias.y);
            float2 o1 = make_float2(cc[2] + bias.x, cc[3] + bias.y);
            *reinterpret_cast<float2*>(out + (size_t)r0 * VV + v)       = o0;
            *reinterpret_cast<float2*>(out + (size_t)(r0 + 8) * VV + v) = o1;
        }
    }
}

// ---------------------------------------------------------------------------
extern "C" void kernel_launch(void* const* d_in, const int* in_sizes, int n_in,
                              void* d_out, int out_size)
{
    const int*   x    = (const int*)  d_in[0];
    const float* emb  = (const float*)d_in[1];
    const float* W_ih = (const float*)d_in[2];
    const float* W_hh = (const float*)d_in[3];
    const float* b_ih = (const float*)d_in[4];
    const float* b_hh = (const float*)d_in[5];
    const float* W_fc = (const float*)d_in[6];
    const float* b_fc = (const float*)d_in[7];
    float* out = (float*)d_out;

    cudaFuncSetAttribute(k_logits_mma, cudaFuncAttributeMaxDynamicSharedMemorySize, SMEM3_BYTES);

    // 1) embedding + input projection
    k_embed_proj<<<BT / 16, 512>>>(x, emb, W_ih, b_ih, b_hh);

    // 1b) W_fc fp16 prep (independent of 1/2)
    k_split_wfc<<<(VPAD * HH) / 256, 256>>>(W_fc);

    // 2) recurrence: 2-CTA cluster per batch (128 CTAs)
    k_lstm<<<BB * 2, 256>>>(W_hh, out, (long long)out_size);

    // 3) logits GEMM on HMMA tensor cores
    dim3 g3(VPAD / 128, BT / 128);
    k_logits_mma<<<g3, 256, SMEM3_BYTES>>>(b_fc, out);
}

// round 11
// speedup vs baseline: 1.1380x; 1.1380x over previous
#include <cuda_runtime.h>
#include <cuda_bf16.h>
#include <cuda_fp16.h>
#include <cstdint>

typedef unsigned long long ull;

// Problem constants (fixed shapes)
#define BB   64
#define TT   256
#define VV   10000
#define VPAD 10240
#define EE   100
#define HH   128
#define GG   512          // 4H
#define BT   (BB*TT)      // 16384
#define KSPLIT 256        // A: [h_hi | h_lo] fp16
#define WKS   128         // B: W_fc fp16 (single copy; shared by hi & lo MMAs)

#define LOGITS_ELEMS ((size_t)BT * VV)          // 163,840,000
#define HF_OFF  LOGITS_ELEMS
#define CF_OFF  (LOGITS_ELEMS + (size_t)BB*HH)
#define FULL_OUT (LOGITS_ELEMS + 2ull*BB*HH)

// Scratch (device globals; allocation-free per harness rules)
__device__ float  g_xproj[(size_t)BT * GG];          // 33.5 MB
__device__ __half g_hs_split[(size_t)BT * KSPLIT];   // 8.4 MB  [bt][hi|lo]
__device__ __half g_wfc_split[(size_t)VPAD * WKS];   // 2.6 MB  [v][hi]

// ---------------------------------------------------------------------------
// Helpers
// ---------------------------------------------------------------------------
__device__ __forceinline__ uint32_t smem_u32(const void* p) {
    uint32_t a;
    asm("{ .reg .u64 t; cvta.to.shared.u64 t, %1; cvt.u32.u64 %0, t; }" : "=r"(a) : "l"(p));
    return a;
}
__device__ __forceinline__ void cp16(uint32_t dst, const void* src) {
    asm volatile("cp.async.cg.shared.global [%0], [%1], 16;" :: "r"(dst), "l"(src));
}
#define CP_COMMIT() asm volatile("cp.async.commit_group;" ::: "memory")
#define CP_WAIT(n)  asm volatile("cp.async.wait_group %0;" :: "n"(n) : "memory")

__device__ __forceinline__ void ldm4(uint32_t* r, uint32_t addr) {
    asm volatile("ldmatrix.sync.aligned.m8n8.x4.shared.b16 {%0,%1,%2,%3}, [%4];"
                 : "=r"(r[0]), "=r"(r[1]), "=r"(r[2]), "=r"(r[3]) : "r"(addr));
}
__device__ __forceinline__ void mma16816(float* c, const uint32_t* a,
                                         uint32_t b0, uint32_t b1) {
    asm volatile(
        "mma.sync.aligned.m16n8k16.row.col.f32.f16.f16.f32 "
        "{%0,%1,%2,%3}, {%4,%5,%6,%7}, {%8,%9}, {%0,%1,%2,%3};"
        : "+f"(c[0]), "+f"(c[1]), "+f"(c[2]), "+f"(c[3])
        : "r"(a[0]), "r"(a[1]), "r"(a[2]), "r"(a[3]), "r"(b0), "r"(b1));
}
__device__ __forceinline__ ull fma2_(ull a, ull b, ull c) {
    ull d;
    asm("fma.rn.f32x2 %0, %1, %2, %3;" : "=l"(d) : "l"(a), "l"(b), "l"(c));
    return d;
}
__device__ __forceinline__ void unpack2_(ull v, float& x, float& y) {
    asm("mov.b64 {%0, %1}, %2;" : "=f"(x), "=f"(y) : "l"(v));
}

// Fast, saturation-safe activations (MUFU EX2 based)
__device__ __forceinline__ float sigm_fast(float x) {
    return 1.f / (1.f + __expf(-x));
}
__device__ __forceinline__ float tanh_fast(float x) {
    return 2.f / (1.f + __expf(-2.f * x)) - 1.f;
}

// ---------------------------------------------------------------------------
// Kernel 1: embedding gather + input projection
// ---------------------------------------------------------------------------
__global__ __launch_bounds__(512) void k_embed_proj(
    const int* __restrict__ x, const float* __restrict__ emb,
    const float* __restrict__ W_ih, const float* __restrict__ b_ih,
    const float* __restrict__ b_hh)
{
    __shared__ float xe_s[16 * EE];
    __shared__ int   toks[16];
    const int bt0 = blockIdx.x * 16;
    const int tid = threadIdx.x;

    if (tid < 16) toks[tid] = x[bt0 + tid];
    __syncthreads();
    for (int i = tid; i < 16 * EE; i += 512) {
        int r = i / EE, e = i - r * EE;
        xe_s[i] = emb[(size_t)toks[r] * EE + e];
    }
    __syncthreads();

    const int g = tid;
    float acc[16];
#pragma unroll
    for (int r = 0; r < 16; r++) acc[r] = 0.f;

    const float4* W4 = reinterpret_cast<const float4*>(W_ih + (size_t)g * EE);
#pragma unroll 5
    for (int e4 = 0; e4 < EE / 4; e4++) {
        float4 w = W4[e4];
#pragma unroll
        for (int r = 0; r < 16; r++) {
            float4 v = reinterpret_cast<const float4*>(xe_s + r * EE)[e4];
            acc[r] += w.x * v.x;
            acc[r] += w.y * v.y;
            acc[r] += w.z * v.z;
            acc[r] += w.w * v.w;
        }
    }
    const float bias = b_ih[g] + b_hh[g];
#pragma unroll
    for (int r = 0; r < 16; r++)
        g_xproj[(size_t)(bt0 + r) * GG + g] = acc[r] + bias;
}

// ---------------------------------------------------------------------------
// Kernel 2: LSTM recurrence (Round-9 proven version).
// 512 threads; W k=0..95 in regs (f32x2), k=96..127 in SMEM pair-quads.
// All-thread combine with replicated c.
// ---------------------------------------------------------------------------
#define KREG  96
#define KSMEM 32
#define SMEM2_BYTES (8*512*16 + (HH + GG) * 4)

__global__ __launch_bounds__(512, 1) void k_lstm(
    const float* __restrict__ W_hh, float* __restrict__ out, long long out_size)
{
    extern __shared__ char smem2raw[];
    ulonglong2* Wt4_s  = reinterpret_cast<ulonglong2*>(smem2raw);      // [8][512]
    float*      h_s    = reinterpret_cast<float*>(smem2raw + 8*512*16); // [128]
    float*      gates_s= h_s + HH;                                      // [512]

    const int b   = blockIdx.x;
    const int tid = threadIdx.x;
    const int q   = tid >> 7;               // gate quarter: 0=i 1=f 2=g 3=o
    const int j   = tid & 127;              // hidden unit owned in combine

    ull wr2[KREG / 2];
    {
        const ulonglong2* Wg = reinterpret_cast<const ulonglong2*>(W_hh + (size_t)tid * HH);
#pragma unroll
        for (int i = 0; i < KREG / 4; i++) {
            ulonglong2 u = Wg[i];
            wr2[2 * i]     = u.x;
            wr2[2 * i + 1] = u.y;
        }
    }
    for (int idx = tid; idx < 8 * 512; idx += 512) {
        int jj = idx >> 9;
        int g2 = idx & 511;
        float4 w4 = *reinterpret_cast<const float4*>(W_hh + (size_t)g2 * HH + KREG + 4 * jj);
        Wt4_s[idx] = *reinterpret_cast<ulonglong2*>(&w4);
    }
    float c = 0.f;                           // replicated 4x across gate quarters
    if (tid < HH) h_s[tid] = 0.f;
    __syncthreads();

    const float* xp = g_xproj + (size_t)b * TT * GG;
    const ulonglong2* h2q = reinterpret_cast<const ulonglong2*>(h_s);

    float xnext = xp[tid];                   // prefetch t=0

    for (int t = 0; t < TT; t++) {
        const float accx = xnext;
        if (t + 1 < TT) xnext = __ldg(xp + (t + 1) * GG + tid);

        ull acc2a = 0ull, acc2b = 0ull;
#pragma unroll
        for (int k4 = 0; k4 < KREG / 4; k4++) {
            ulonglong2 hp = h2q[k4];         // LDS.128 broadcast
            acc2a = fma2_(wr2[2 * k4],     hp.x, acc2a);
            acc2b = fma2_(wr2[2 * k4 + 1], hp.y, acc2b);
        }
#pragma unroll
        for (int jj = 0; jj < 8; jj++) {
            ulonglong2 hp = h2q[KREG / 4 + jj];
            ulonglong2 wv = Wt4_s[(jj << 9) + tid];
            acc2a = fma2_(wv.x, hp.x, acc2a);
            acc2b = fma2_(wv.y, hp.y, acc2b);
        }
        float l0, h0, l1, h1;
        unpack2_(acc2a, l0, h0);
        unpack2_(acc2b, l1, h1);
        const float gv = accx + ((l0 + l1) + (h0 + h1));

        gates_s[tid] = (q == 2) ? tanh_fast(gv) : sigm_fast(gv);
        __syncthreads();

        // All threads combine (c replicated; deterministic identical updates)
        {
            float ig = gates_s[j];
            float fg = gates_s[HH + j];
            float gg = gates_s[2 * HH + j];
            float og = gates_s[3 * HH + j];
            c = fg * c + ig * gg;
            float h = og * tanh_fast(c);
            if (tid < HH) {
                h_s[j] = h;
                __half hh = __float2half_rn(h);
                float  hl = h - __half2float(hh);
                size_t base = ((size_t)b * TT + t) * KSPLIT;
                g_hs_split[base + j]       = hh;
                g_hs_split[base + 128 + j] = __float2half_rn(hl);
            }
        }
        __syncthreads();
    }

    if (tid < HH && out_size >= (long long)FULL_OUT) {
        out[HF_OFF + (size_t)b * HH + tid] = h_s[tid];
        out[CF_OFF + (size_t)b * HH + tid] = c;
    }
}

// ---------------------------------------------------------------------------
// Kernel 2b: W_fc -> fp16, single copy, zero-padded to VPAD rows
// ---------------------------------------------------------------------------
__global__ __launch_bounds__(256) void k_split_wfc(const float* __restrict__ W_fc)
{
    size_t i = (size_t)blockIdx.x * 256 + threadIdx.x;   // over VPAD*128
    int v = (int)(i >> 7);
    float w = (v < VV) ? W_fc[i] : 0.f;
    g_wfc_split[i] = __float2half_rn(w);
}

// ---------------------------------------------------------------------------
// Kernel 3: logits GEMM via mma.sync. fp16 2-term with SHARED B:
// per k-chunk load A_hi, A_lo and ONE B tile; run both MMA sets against the
// same B registers. 128x128 block tile, 2 chunks of BK=64, double-buffered.
// 8 warps as 2(m) x 4(n); warp tile 64x32.
// ---------------------------------------------------------------------------
#define NK 2
#define STAGE_BYTES 49152          // A_hi 16KB + A_lo 16KB + B 16KB
#define SMEM3_BYTES (2 * STAGE_BYTES)

__device__ __forceinline__ void load_chunk(
    uint32_t smem_base, int stage,
    const __half* __restrict__ asrc,   // + bt0*KSPLIT
    const __half* __restrict__ bsrc,   // + v0*WKS
    int kc, int tid)
{
    const int ahbuf = stage * STAGE_BYTES;
    const int albuf = ahbuf + 16384;
    const int bbuf  = ahbuf + 32768;
    const int k0 = kc * 64;
#pragma unroll
    for (int it = 0; it < 4; it++) {          // A_hi: 128 rows x 8 chunks
        int i = tid + it * 256;
        int row = i >> 3;
        int jj  = i & 7;
        uint32_t dst = smem_base + ahbuf + row * 128 + ((jj ^ (row & 7)) << 4);
        cp16(dst, asrc + (size_t)row * KSPLIT + k0 + jj * 8);
    }
#pragma unroll
    for (int it = 0; it < 4; it++) {          // A_lo
        int i = tid + it * 256;
        int row = i >> 3;
        int jj  = i & 7;
        uint32_t dst = smem_base + albuf + row * 128 + ((jj ^ (row & 7)) << 4);
        cp16(dst, asrc + (size_t)row * KSPLIT + 128 + k0 + jj * 8);
    }
#pragma unroll
    for (int it = 0; it < 4; it++) {          // B (single copy of W)
        int i = tid + it * 256;
        int row = i >> 3;
        int jj  = i & 7;
        uint32_t dst = smem_base + bbuf + row * 128 + ((jj ^ (row & 7)) << 4);
        cp16(dst, bsrc + (size_t)row * WKS + k0 + jj * 8);
    }
}

__global__ __launch_bounds__(256, 2) void k_logits_mma(
    const float* __restrict__ b_fc, float* __restrict__ out)
{
    extern __shared__ char smem3[];
    const uint32_t smem_base = smem_u32(smem3);
    const int tid = threadIdx.x;
    const int wid = tid >> 5;
    const int l   = tid & 31;
    const int v0  = blockIdx.x * 128;
    const int bt0 = blockIdx.y * 128;

    const __half* asrc = g_hs_split + (size_t)bt0 * KSPLIT;
    const __half* bsrc = g_wfc_split + (size_t)v0 * WKS;

    const int wm = (wid >> 2) * 64;   // warp m offset (0/64)
    const int wn = (wid & 3) * 32;    // warp n offset (0..96)

    float c[4][4][4];
#pragma unroll
    for (int mi = 0; mi < 4; mi++)
#pragma unroll
        for (int nj = 0; nj < 4; nj++)
#pragma unroll
            for (int qq = 0; qq < 4; qq++) c[mi][nj][qq] = 0.f;

    const int lrow = l & 15;
    const int lsel = l >> 4;

    // prologue: both chunks in flight
    load_chunk(smem_base, 0, asrc, bsrc, 0, tid);
    CP_COMMIT();
    load_chunk(smem_base, 1, asrc, bsrc, 1, tid);
    CP_COMMIT();

#pragma unroll
    for (int kc = 0; kc < NK; kc++) {
        if (kc == 0) { CP_WAIT(1); } else { CP_WAIT(0); }
        __syncthreads();                       // chunk kc visible to all threads

        const int ahbuf = kc * STAGE_BYTES;
        const int albuf = ahbuf + 16384;
        const int bbuf  = ahbuf + 32768;
#pragma unroll
        for (int k16 = 0; k16 < 4; k16++) {
            const int jj = 2 * k16 + lsel;
            // B once per k16, shared by hi and lo passes
            uint32_t bfr[2][4];
#pragma unroll
            for (int njp = 0; njp < 2; njp++) {
                int r = wn + njp * 16 + lrow;
                ldm4(bfr[njp], smem_base + bbuf + r * 128 + ((jj ^ (r & 7)) << 4));
            }
            // pass 1: A_hi
            uint32_t a[4][4];
#pragma unroll
            for (int mi = 0; mi < 4; mi++) {
                int r = wm + mi * 16 + lrow;
                ldm4(a[mi], smem_base + ahbuf + r * 128 + ((jj ^ (r & 7)) << 4));
            }
#pragma unroll
            for (int mi = 0; mi < 4; mi++) {
#pragma unroll
                for (int njp = 0; njp < 2; njp++) {
                    mma16816(c[mi][njp * 2 + 0], a[mi], bfr[njp][0], bfr[njp][2]);
                    mma16816(c[mi][njp * 2 + 1], a[mi], bfr[njp][1], bfr[njp][3]);
                }
            }
            // pass 2: A_lo (reuse same registers + same B)
#pragma unroll
            for (int mi = 0; mi < 4; mi++) {
                int r = wm + mi * 16 + lrow;
                ldm4(a[mi], smem_base + albuf + r * 128 + ((jj ^ (r & 7)) << 4));
            }
#pragma unroll
            for (int mi = 0; mi < 4; mi++) {
#pragma unroll
                for (int njp = 0; njp < 2; njp++) {
                    mma16816(c[mi][njp * 2 + 0], a[mi], bfr[njp][0], bfr[njp][2]);
                    mma16816(c[mi][njp * 2 + 1], a[mi], bfr[njp][1], bfr[njp][3]);
                }
            }
        }
    }

    // Epilogue: bias + guarded float2 stores
    const int g  = l >> 2;
    const int qq = l & 3;
    const int mB = bt0 + wm;
    const int nB = v0 + wn;

#pragma unroll
    for (int nj = 0; nj < 4; nj++) {
        const int v = nB + nj * 8 + 2 * qq;
        if (v >= VV) continue;
        const float2 bias = *reinterpret_cast<const float2*>(b_fc + v);
#pragma unroll
        for (int mi = 0; mi < 4; mi++) {
            const float* cc = c[mi][nj];
            const int r0 = mB + mi * 16 + g;
            float2 o0 = make_float2(cc[0] + bias.x, cc[1] + bias.y);
            float2 o1 = make_float2(cc[2] + bias.x, cc[3] + bias.y);
            *reinterpret_cast<float2*>(out + (size_t)r0 * VV + v)       = o0;
            *reinterpret_cast<float2*>(out + (size_t)(r0 + 8) * VV + v) = o1;
        }
    }
}

// ---------------------------------------------------------------------------
extern "C" void kernel_launch(void* const* d_in, const int* in_sizes, int n_in,
                              void* d_out, int out_size)
{
    const int*   x    = (const int*)  d_in[0];
    const float* emb  = (const float*)d_in[1];
    const float* W_ih = (const float*)d_in[2];
    const float* W_hh = (const float*)d_in[3];
    const float* b_ih = (const float*)d_in[4];
    const float* b_hh = (const float*)d_in[5];
    const float* W_fc = (const float*)d_in[6];
    const float* b_fc = (const float*)d_in[7];
    float* out = (float*)d_out;

    cudaFuncSetAttribute(k_lstm,       cudaFuncAttributeMaxDynamicSharedMemorySize, SMEM2_BYTES);
    cudaFuncSetAttribute(k_logits_mma, cudaFuncAttributeMaxDynamicSharedMemorySize, SMEM3_BYTES);

    // 1) embedding + input projection
    k_embed_proj<<<BT / 16, 512>>>(x, emb, W_ih, b_ih, b_hh);

    // 1b) W_fc fp16 prep (independent of 1/2)
    k_split_wfc<<<(VPAD * WKS) / 256, 256>>>(W_fc);

    // 2) recurrence (writes hs split + h_n/c_n tail of out)
    k_lstm<<<BB, 512, SMEM2_BYTES>>>(W_hh, out, (long long)out_size);

    // 3) logits GEMM on HMMA tensor cores
    dim3 g3(VPAD / 128, BT / 128);
    k_logits_mma<<<g3, 256, SMEM3_BYTES>>>(b_fc, out);
}

// round 12
// speedup vs baseline: 1.1635x; 1.0224x over previous
#include <cuda_runtime.h>
#include <cuda_bf16.h>
#include <cuda_fp16.h>
#include <cstdint>

typedef unsigned long long ull;

// Problem constants (fixed shapes)
#define BB   64
#define TT   256
#define VV   10000
#define VPAD 10240
#define EE   100
#define HH   128
#define GG   512          // 4H
#define BT   (BB*TT)      // 16384
#define KSPLIT 256        // A: [h_hi | h_lo] fp16
#define WKS   128         // B: W_fc fp16 (single copy; shared by hi & lo MMAs)

#define LOGITS_ELEMS ((size_t)BT * VV)          // 163,840,000
#define HF_OFF  LOGITS_ELEMS
#define CF_OFF  (LOGITS_ELEMS + (size_t)BB*HH)
#define FULL_OUT (LOGITS_ELEMS + 2ull*BB*HH)

// Scratch (device globals; allocation-free per harness rules)
__device__ float  g_xproj[(size_t)BT * GG];          // 33.5 MB
__device__ __half g_hs_split[(size_t)BT * KSPLIT];   // 8.4 MB  [bt][hi|lo]
__device__ __half g_wfc_split[(size_t)VPAD * WKS];   // 2.6 MB  [v][hi]

// ---------------------------------------------------------------------------
// Helpers
// ---------------------------------------------------------------------------
__device__ __forceinline__ uint32_t smem_u32(const void* p) {
    uint32_t a;
    asm("{ .reg .u64 t; cvta.to.shared.u64 t, %1; cvt.u32.u64 %0, t; }" : "=r"(a) : "l"(p));
    return a;
}
__device__ __forceinline__ void cp16(uint32_t dst, const void* src) {
    asm volatile("cp.async.cg.shared.global [%0], [%1], 16;" :: "r"(dst), "l"(src));
}
#define CP_COMMIT() asm volatile("cp.async.commit_group;" ::: "memory")
#define CP_WAIT(n)  asm volatile("cp.async.wait_group %0;" :: "n"(n) : "memory")

__device__ __forceinline__ void ldm4(uint32_t* r, uint32_t addr) {
    asm volatile("ldmatrix.sync.aligned.m8n8.x4.shared.b16 {%0,%1,%2,%3}, [%4];"
                 : "=r"(r[0]), "=r"(r[1]), "=r"(r[2]), "=r"(r[3]) : "r"(addr));
}
__device__ __forceinline__ void mma16816(float* c, const uint32_t* a,
                                         uint32_t b0, uint32_t b1) {
    asm volatile(
        "mma.sync.aligned.m16n8k16.row.col.f32.f16.f16.f32 "
        "{%0,%1,%2,%3}, {%4,%5,%6,%7}, {%8,%9}, {%0,%1,%2,%3};"
        : "+f"(c[0]), "+f"(c[1]), "+f"(c[2]), "+f"(c[3])
        : "r"(a[0]), "r"(a[1]), "r"(a[2]), "r"(a[3]), "r"(b0), "r"(b1));
}
__device__ __forceinline__ ull fma2_(ull a, ull b, ull c) {
    ull d;
    asm("fma.rn.f32x2 %0, %1, %2, %3;" : "=l"(d) : "l"(a), "l"(b), "l"(c));
    return d;
}
__device__ __forceinline__ void unpack2_(ull v, float& x, float& y) {
    asm("mov.b64 {%0, %1}, %2;" : "=f"(x), "=f"(y) : "l"(v));
}

// Fast, saturation-safe activations (MUFU EX2 based)
__device__ __forceinline__ float sigm_fast(float x) {
    return 1.f / (1.f + __expf(-x));
}
__device__ __forceinline__ float tanh_fast(float x) {
    return 2.f / (1.f + __expf(-2.f * x)) - 1.f;
}

// ---------------------------------------------------------------------------
// Kernel 1: embedding gather + input projection.
// 256 threads, each owns TWO gate rows (g, g+256) -> per 16B xe LDS.128 we do
// 8 MACs (was 4), halving the smem-crossbar time that bound this kernel.
// ---------------------------------------------------------------------------
__global__ __launch_bounds__(256) void k_embed_proj(
    const int* __restrict__ x, const float* __restrict__ emb,
    const float* __restrict__ W_ih, const float* __restrict__ b_ih,
    const float* __restrict__ b_hh)
{
    __shared__ float4 xe_s[16][25];          // 16 rows x 100 floats
    __shared__ int    toks[16];
    const int bt0 = blockIdx.x * 16;
    const int tid = threadIdx.x;

    if (tid < 16) toks[tid] = x[bt0 + tid];
    __syncthreads();
    for (int i = tid; i < 16 * 25; i += 256) {
        int r = i / 25, e4 = i - r * 25;
        xe_s[r][e4] = *reinterpret_cast<const float4*>(emb + (size_t)toks[r] * EE + 4 * e4);
    }
    __syncthreads();

    const int g0 = tid;
    const int g1 = tid + 256;
    float acc0[16], acc1[16];
#pragma unroll
    for (int r = 0; r < 16; r++) { acc0[r] = 0.f; acc1[r] = 0.f; }

    const float4* W0 = reinterpret_cast<const float4*>(W_ih + (size_t)g0 * EE);
    const float4* W1 = reinterpret_cast<const float4*>(W_ih + (size_t)g1 * EE);
    float4 w0 = W0[0], w1 = W1[0];

    for (int e4 = 0; e4 < 25; e4++) {
        const float4 w0c = w0, w1c = w1;
        if (e4 + 1 < 25) { w0 = W0[e4 + 1]; w1 = W1[e4 + 1]; }   // prefetch
#pragma unroll
        for (int r = 0; r < 16; r++) {
            const float4 v = xe_s[r][e4];    // LDS.128 broadcast
            acc0[r] += w0c.x * v.x; acc1[r] += w1c.x * v.x;
            acc0[r] += w0c.y * v.y; acc1[r] += w1c.y * v.y;
            acc0[r] += w0c.z * v.z; acc1[r] += w1c.z * v.z;
            acc0[r] += w0c.w * v.w; acc1[r] += w1c.w * v.w;
        }
    }
    const float bias0 = b_ih[g0] + b_hh[g0];
    const float bias1 = b_ih[g1] + b_hh[g1];
#pragma unroll
    for (int r = 0; r < 16; r++) {
        g_xproj[(size_t)(bt0 + r) * GG + g0] = acc0[r] + bias0;
        g_xproj[(size_t)(bt0 + r) * GG + g1] = acc1[r] + bias1;
    }
}

// ---------------------------------------------------------------------------
// Kernel 2: LSTM recurrence (Round-9 proven version).
// 512 threads; W k=0..95 in regs (f32x2), k=96..127 in SMEM pair-quads.
// All-thread combine with replicated c.
// ---------------------------------------------------------------------------
#define KREG  96
#define KSMEM 32
#define SMEM2_BYTES (8*512*16 + (HH + GG) * 4)

__global__ __launch_bounds__(512, 1) void k_lstm(
    const float* __restrict__ W_hh, float* __restrict__ out, long long out_size)
{
    extern __shared__ char smem2raw[];
    ulonglong2* Wt4_s  = reinterpret_cast<ulonglong2*>(smem2raw);      // [8][512]
    float*      h_s    = reinterpret_cast<float*>(smem2raw + 8*512*16); // [128]
    float*      gates_s= h_s + HH;                                      // [512]

    const int b   = blockIdx.x;
    const int tid = threadIdx.x;
    const int q   = tid >> 7;               // gate quarter: 0=i 1=f 2=g 3=o
    const int j   = tid & 127;              // hidden unit owned in combine

    ull wr2[KREG / 2];
    {
        const ulonglong2* Wg = reinterpret_cast<const ulonglong2*>(W_hh + (size_t)tid * HH);
#pragma unroll
        for (int i = 0; i < KREG / 4; i++) {
            ulonglong2 u = Wg[i];
            wr2[2 * i]     = u.x;
            wr2[2 * i + 1] = u.y;
        }
    }
    for (int idx = tid; idx < 8 * 512; idx += 512) {
        int jj = idx >> 9;
        int g2 = idx & 511;
        float4 w4 = *reinterpret_cast<const float4*>(W_hh + (size_t)g2 * HH + KREG + 4 * jj);
        Wt4_s[idx] = *reinterpret_cast<ulonglong2*>(&w4);
    }
    float c = 0.f;                           // replicated 4x across gate quarters
    if (tid < HH) h_s[tid] = 0.f;
    __syncthreads();

    const float* xp = g_xproj + (size_t)b * TT * GG;
    const ulonglong2* h2q = reinterpret_cast<const ulonglong2*>(h_s);

    float xnext = xp[tid];                   // prefetch t=0

    for (int t = 0; t < TT; t++) {
        const float accx = xnext;
        if (t + 1 < TT) xnext = __ldg(xp + (t + 1) * GG + tid);

        ull acc2a = 0ull, acc2b = 0ull;
#pragma unroll
        for (int k4 = 0; k4 < KREG / 4; k4++) {
            ulonglong2 hp = h2q[k4];         // LDS.128 broadcast
            acc2a = fma2_(wr2[2 * k4],     hp.x, acc2a);
            acc2b = fma2_(wr2[2 * k4 + 1], hp.y, acc2b);
        }
#pragma unroll
        for (int jj = 0; jj < 8; jj++) {
            ulonglong2 hp = h2q[KREG / 4 + jj];
            ulonglong2 wv = Wt4_s[(jj << 9) + tid];
            acc2a = fma2_(wv.x, hp.x, acc2a);
            acc2b = fma2_(wv.y, hp.y, acc2b);
        }
        float l0, h0, l1, h1;
        unpack2_(acc2a, l0, h0);
        unpack2_(acc2b, l1, h1);
        const float gv = accx + ((l0 + l1) + (h0 + h1));

        gates_s[tid] = (q == 2) ? tanh_fast(gv) : sigm_fast(gv);
        __syncthreads();

        // All threads combine (c replicated; deterministic identical updates)
        {
            float ig = gates_s[j];
            float fg = gates_s[HH + j];
            float gg = gates_s[2 * HH + j];
            float og = gates_s[3 * HH + j];
            c = fg * c + ig * gg;
            float h = og * tanh_fast(c);
            if (tid < HH) {
                h_s[j] = h;
                __half hh = __float2half_rn(h);
                float  hl = h - __half2float(hh);
                size_t base = ((size_t)b * TT + t) * KSPLIT;
                g_hs_split[base + j]       = hh;
                g_hs_split[base + 128 + j] = __float2half_rn(hl);
            }
        }
        __syncthreads();
    }

    if (tid < HH && out_size >= (long long)FULL_OUT) {
        out[HF_OFF + (size_t)b * HH + tid] = h_s[tid];
        out[CF_OFF + (size_t)b * HH + tid] = c;
    }
}

// ---------------------------------------------------------------------------
// Kernel 2b: W_fc -> fp16, single copy, zero-padded to VPAD rows
// ---------------------------------------------------------------------------
__global__ __launch_bounds__(256) void k_split_wfc(const float* __restrict__ W_fc)
{
    size_t i = (size_t)blockIdx.x * 256 + threadIdx.x;   // over VPAD*128
    int v = (int)(i >> 7);
    float w = (v < VV) ? W_fc[i] : 0.f;
    g_wfc_split[i] = __float2half_rn(w);
}

// ---------------------------------------------------------------------------
// Kernel 3: logits GEMM via mma.sync. fp16 2-term with shared B, FULL-K
// resident: A_hi 32K | A_lo 32K | B 32K = 96KB loaded once; mainloop is 8
// unbroken k16 iterations with NO barriers/waits -> ptxas pipelines LDSM
// across MMA blocks freely. 8 warps as 2(m) x 4(n); warp tile 64x32.
// Rows are 256B (16 chunks of 16B); swizzle per 128B half-row (as 2 BK=64
// column blocks): addr = r*256 + (j>>3)*128 + (((j&7)^(r&7))<<4).
// ---------------------------------------------------------------------------
#define SMEM3_BYTES (96 * 1024)

__global__ __launch_bounds__(256, 2) void k_logits_mma(
    const float* __restrict__ b_fc, float* __restrict__ out)
{
    extern __shared__ char smem3[];
    const uint32_t smem_base = smem_u32(smem3);
    const int tid = threadIdx.x;
    const int wid = tid >> 5;
    const int l   = tid & 31;
    const int v0  = blockIdx.x * 128;
    const int bt0 = blockIdx.y * 128;

    const __half* asrc = g_hs_split + (size_t)bt0 * KSPLIT;
    const __half* bsrc = g_wfc_split + (size_t)v0 * WKS;

    const int AHI = 0, ALO = 32768, BBF = 65536;

    // Load everything: 3 tiles x 128 rows x 16 chunks of 16B, 24 cp16/thread
#pragma unroll
    for (int it = 0; it < 8; it++) {
        int i = tid + it * 256;              // 0..2047
        int row = i >> 4;
        int j   = i & 15;
        uint32_t off = (uint32_t)row * 256 + ((j >> 3) << 7) + (((j & 7) ^ (row & 7)) << 4);
        cp16(smem_base + AHI + off, asrc + (size_t)row * KSPLIT + j * 8);
        cp16(smem_base + ALO + off, asrc + (size_t)row * KSPLIT + 128 + j * 8);
        cp16(smem_base + BBF + off, bsrc + (size_t)row * WKS + j * 8);
    }
    CP_COMMIT();

    const int wm = (wid >> 2) * 64;   // warp m offset (0/64)
    const int wn = (wid & 3) * 32;    // warp n offset (0..96)

    float c[4][4][4];
#pragma unroll
    for (int mi = 0; mi < 4; mi++)
#pragma unroll
        for (int nj = 0; nj < 4; nj++)
#pragma unroll
            for (int qq = 0; qq < 4; qq++) c[mi][nj][qq] = 0.f;

    const int lrow = l & 15;
    const int lsel = l >> 4;

    CP_WAIT(0);
    __syncthreads();                  // only barrier in the whole kernel

#pragma unroll
    for (int k16 = 0; k16 < 8; k16++) {
        const int jj = 2 * k16 + lsel;               // 0..15
        const uint32_t joff = ((jj >> 3) << 7) + (((jj & 7) ^ (lrow & 7)) << 4);
        // NB: swizzle depends on r&7 = lrow&7 (r = base + multiple of 16 + lrow)

        uint32_t bfr[2][4];
#pragma unroll
        for (int njp = 0; njp < 2; njp++) {
            int r = wn + njp * 16 + lrow;
            ldm4(bfr[njp], smem_base + BBF + (uint32_t)r * 256 + joff);
        }
        uint32_t a[4][4];
#pragma unroll
        for (int mi = 0; mi < 4; mi++) {
            int r = wm + mi * 16 + lrow;
            ldm4(a[mi], smem_base + AHI + (uint32_t)r * 256 + joff);
        }
#pragma unroll
        for (int mi = 0; mi < 4; mi++) {
#pragma unroll
            for (int njp = 0; njp < 2; njp++) {
                mma16816(c[mi][njp * 2 + 0], a[mi], bfr[njp][0], bfr[njp][2]);
                mma16816(c[mi][njp * 2 + 1], a[mi], bfr[njp][1], bfr[njp][3]);
            }
        }
        uint32_t alo[4][4];
#pragma unroll
        for (int mi = 0; mi < 4; mi++) {
            int r = wm + mi * 16 + lrow;
            ldm4(alo[mi], smem_base + ALO + (uint32_t)r * 256 + joff);
        }
#pragma unroll
        for (int mi = 0; mi < 4; mi++) {
#pragma unroll
            for (int njp = 0; njp < 2; njp++) {
                mma16816(c[mi][njp * 2 + 0], alo[mi], bfr[njp][0], bfr[njp][2]);
                mma16816(c[mi][njp * 2 + 1], alo[mi], bfr[njp][1], bfr[njp][3]);
            }
        }
    }

    // Epilogue: bias + guarded float2 stores
    const int g  = l >> 2;
    const int qq = l & 3;
    const int mB = bt0 + wm;
    const int nB = v0 + wn;

#pragma unroll
    for (int nj = 0; nj < 4; nj++) {
        const int v = nB + nj * 8 + 2 * qq;
        if (v >= VV) continue;
        const float2 bias = *reinterpret_cast<const float2*>(b_fc + v);
#pragma unroll
        for (int mi = 0; mi < 4; mi++) {
            const float* cc = c[mi][nj];
            const int r0 = mB + mi * 16 + g;
            float2 o0 = make_float2(cc[0] + bias.x, cc[1] + bias.y);
            float2 o1 = make_float2(cc[2] + bias.x, cc[3] + bias.y);
            *reinterpret_cast<float2*>(out + (size_t)r0 * VV + v)       = o0;
            *reinterpret_cast<float2*>(out + (size_t)(r0 + 8) * VV + v) = o1;
        }
    }
}

// ---------------------------------------------------------------------------
extern "C" void kernel_launch(void* const* d_in, const int* in_sizes, int n_in,
                              void* d_out, int out_size)
{
    const int*   x    = (const int*)  d_in[0];
    const float* emb  = (const float*)d_in[1];
    const float* W_ih = (const float*)d_in[2];
    const float* W_hh = (const float*)d_in[3];
    const float* b_ih = (const float*)d_in[4];
    const float* b_hh = (const float*)d_in[5];
    const float* W_fc = (const float*)d_in[6];
    const float* b_fc = (const float*)d_in[7];
    float* out = (float*)d_out;

    cudaFuncSetAttribute(k_lstm,       cudaFuncAttributeMaxDynamicSharedMemorySize, SMEM2_BYTES);
    cudaFuncSetAttribute(k_logits_mma, cudaFuncAttributeMaxDynamicSharedMemorySize, SMEM3_BYTES);

    // 1) embedding + input projection
    k_embed_proj<<<BT / 16, 256>>>(x, emb, W_ih, b_ih, b_hh);

    // 1b) W_fc fp16 prep (independent of 1/2)
    k_split_wfc<<<(VPAD * WKS) / 256, 256>>>(W_fc);

    // 2) recurrence (writes hs split + h_n/c_n tail of out)
    k_lstm<<<BB, 512, SMEM2_BYTES>>>(W_hh, out, (long long)out_size);

    // 3) logits GEMM on HMMA tensor cores
    dim3 g3(VPAD / 128, BT / 128);
    k_logits_mma<<<g3, 256, SMEM3_BYTES>>>(b_fc, out);
}